// round 1
// baseline (speedup 1.0000x reference)
#include <cuda_runtime.h>
#include <cuda_bf16.h>

// SymmetryLoss: chamfer(mirror(xyz), xyz) with yz-plane mirror.
// xyz: (B=16, 3, N=4096) float32, NCHW. Output: scalar float loss.
//
// Exploits d2 symmetry (mirror is an involutive isometry):
//   loss = (2/(B*N)) * sum_{b,n} min_m d2[b][n][m]
// Inner form: d2 = a2_n + (b2_m - 2 a.b)  -> 3 FFMA + 1 FMNMX per pair.

#define BATCH   16
#define NPTS    4096
#define THREADS 256
#define UPT     2                 // n-points per thread
#define CHUNK   (THREADS * UPT)   // 512 n-points per block
#define NCHUNK  (NPTS / CHUNK)    // 8
#define GRID    (BATCH * NCHUNK)  // 128 blocks
#define TILE    2048              // m-points per smem tile (32 KB float4)

__device__ float g_partials[GRID];

__global__ __launch_bounds__(THREADS, 2)
void chamfer_sym_kernel(const float* __restrict__ xyz)
{
    __shared__ float4 sm[TILE];
    __shared__ float  red[THREADS / 32];

    const int blk = blockIdx.x;
    const int b   = blk >> 3;          // / NCHUNK
    const int c   = blk & (NCHUNK - 1);
    const int t   = threadIdx.x;

    const float* __restrict__ px = xyz + (size_t)b * 3 * NPTS;
    const float* __restrict__ py = px + NPTS;
    const float* __restrict__ pz = px + 2 * NPTS;

    // Load this thread's mirrored a-points: a = (-x, y, z); a2 = x^2+y^2+z^2.
    float ax[UPT], ay[UPT], az[UPT], a2[UPT], emin[UPT];
#pragma unroll
    for (int u = 0; u < UPT; u++) {
        const int n = c * CHUNK + u * THREADS + t;
        const float x = px[n], y = py[n], z = pz[n];
        ax[u] = -x; ay[u] = y; az[u] = z;
        a2[u] = x * x + y * y + z * z;
        emin[u] = 3.4e38f;
    }

    for (int tile = 0; tile < NPTS; tile += TILE) {
        __syncthreads();  // protect smem from previous pass readers
        // Cooperative tile load: sm[j] = (-2x, -2y, -2z, x^2+y^2+z^2)
        for (int j = t; j < TILE; j += THREADS) {
            const int m = tile + j;
            const float x = px[m], y = py[m], z = pz[m];
            sm[j] = make_float4(-2.f * x, -2.f * y, -2.f * z,
                                x * x + y * y + z * z);
        }
        __syncthreads();

#pragma unroll 8
        for (int j = 0; j < TILE; j++) {
            const float4 s = sm[j];   // broadcast LDS.128 (conflict-free)
#pragma unroll
            for (int u = 0; u < UPT; u++) {
                // e = b2 - 2 a.b   (3 dependent FFMAs)
                float e = fmaf(ax[u], s.x,
                          fmaf(ay[u], s.y,
                          fmaf(az[u], s.z, s.w)));
                emin[u] = fminf(emin[u], e);
            }
        }
    }

    // dist12[n] = a2_n + emin_n ; sum over this thread's points
    float sum = 0.f;
#pragma unroll
    for (int u = 0; u < UPT; u++)
        sum += a2[u] + emin[u];

    // Deterministic block reduction: warp shuffle, then cross-warp via smem.
#pragma unroll
    for (int off = 16; off > 0; off >>= 1)
        sum += __shfl_down_sync(0xFFFFFFFFu, sum, off);

    const int wid = t >> 5;
    if ((t & 31) == 0) red[wid] = sum;
    __syncthreads();
    if (t == 0) {
        float s = 0.f;
#pragma unroll
        for (int w = 0; w < THREADS / 32; w++) s += red[w];
        g_partials[blk] = s;
    }
}

__global__ void finish_kernel(float* __restrict__ out)
{
    __shared__ float red[4];
    const int t = threadIdx.x;         // 128 threads
    float v = g_partials[t];
#pragma unroll
    for (int off = 16; off > 0; off >>= 1)
        v += __shfl_down_sync(0xFFFFFFFFu, v, off);
    if ((t & 31) == 0) red[t >> 5] = v;
    __syncthreads();
    if (t == 0) {
        float s = red[0] + red[1] + red[2] + red[3];
        // loss = mean_b(mean12 + mean21) = 2/(B*N) * total
        out[0] = s * (2.0f / (float)(BATCH * NPTS));
    }
}

extern "C" void kernel_launch(void* const* d_in, const int* in_sizes, int n_in,
                              void* d_out, int out_size)
{
    (void)in_sizes; (void)n_in; (void)out_size;
    const float* xyz = (const float*)d_in[0];
    float* out = (float*)d_out;

    chamfer_sym_kernel<<<GRID, THREADS>>>(xyz);
    finish_kernel<<<1, GRID>>>(out);
}